// round 8
// baseline (speedup 1.0000x reference)
#include <cuda_runtime.h>
#include <cuda_bf16.h>
#include <cstdint>

#define NN 20000
#define DD 128
#define EE 32768
#define RR 474
#define BB 64
#define GB 32          // grouping blocks
#define GT 256         // grouping threads
#define EPB (EE / GB)  // 1024 edges per grouping block

// ---------------- device scratch ----------------
__device__ float g_X[NN * DD];
__device__ float g_H[NN * DD];
__device__ float g_W1[RR * DD * DD];
__device__ float g_W2[RR * DD * DD];
__device__ float g_alpha[EE];
__device__ float g_denom0[NN];
__device__ float g_denom1[NN];
__device__ int   g_bh[GB * RR];
__device__ int   g_bstart[GB * RR];
__device__ int   g_offs[RR + 1];
__device__ int   g_order[EE];

// ---------------- mma helpers ----------------
__device__ __forceinline__ void mma_bf16(float* d, const uint32_t* a, const uint32_t* b) {
    asm volatile(
        "mma.sync.aligned.m16n8k16.row.col.f32.bf16.bf16.f32 "
        "{%0,%1,%2,%3}, {%4,%5,%6,%7}, {%8,%9}, {%0,%1,%2,%3};"
        : "+f"(d[0]), "+f"(d[1]), "+f"(d[2]), "+f"(d[3])
        : "r"(a[0]), "r"(a[1]), "r"(a[2]), "r"(a[3]), "r"(b[0]), "r"(b[1]));
}
__device__ __forceinline__ uint32_t pack2_bf16(float a, float b) {
    __nv_bfloat162 p = __floats2bfloat162_rn(a, b);
    return *reinterpret_cast<uint32_t*>(&p);
}
__device__ __forceinline__ void split_bf16(float v, __nv_bfloat16& h, float& lo) {
    h = __float2bfloat16(v);
    lo = v - __bfloat162float(h);
}

// ================= W build: C[M,16384] = A[M,64] @ B[64,16384] =================
#define WB_STRIDE 72
#define WB_A_HI 0
#define WB_A_LO (128 * WB_STRIDE * 2)
#define WB_B_HI (2 * 128 * WB_STRIDE * 2)
#define WB_B_LO (3 * 128 * WB_STRIDE * 2)
#define WB_SMEM (4 * 128 * WB_STRIDE * 2)

__global__ void __launch_bounds__(256, 1)
k_wbuild(const float* __restrict__ A, const float* __restrict__ B,
         float* __restrict__ C, int M) {
    extern __shared__ char smem[];
    __nv_bfloat16* sAh = (__nv_bfloat16*)(smem + WB_A_HI);
    __nv_bfloat16* sAl = (__nv_bfloat16*)(smem + WB_A_LO);
    __nv_bfloat16* sBh = (__nv_bfloat16*)(smem + WB_B_HI);
    __nv_bfloat16* sBl = (__nv_bfloat16*)(smem + WB_B_LO);

    int t = threadIdx.x;
    int n0 = blockIdx.x * 128, m0 = blockIdx.y * 128;

    #pragma unroll
    for (int e = t; e < 128 * 64; e += 256) {
        int m = e >> 6, k = e & 63;
        float v = (m0 + m < M) ? A[(m0 + m) * 64 + k] : 0.f;
        __nv_bfloat16 h; float lo;
        split_bf16(v, h, lo);
        sAh[m * WB_STRIDE + k] = h;
        sAl[m * WB_STRIDE + k] = __float2bfloat16(lo);
    }
    #pragma unroll
    for (int e = t; e < 64 * 128; e += 256) {
        int k = e >> 7, n = e & 127;
        float v = B[(size_t)k * 16384 + n0 + n];
        __nv_bfloat16 h; float lo;
        split_bf16(v, h, lo);
        sBh[n * WB_STRIDE + k] = h;
        sBl[n * WB_STRIDE + k] = __float2bfloat16(lo);
    }
    __syncthreads();

    int wid = t >> 5, lane = t & 31;
    int warpM = wid >> 2, warpN = wid & 3;
    int g = lane >> 2, tg = lane & 3;

    float acc[4][4][4];
    #pragma unroll
    for (int i = 0; i < 4; i++)
        #pragma unroll
        for (int j = 0; j < 4; j++)
            #pragma unroll
            for (int q = 0; q < 4; q++) acc[i][j][q] = 0.f;

    #pragma unroll
    for (int ks = 0; ks < 4; ks++) {
        int kk = ks * 16 + tg * 2;
        uint32_t ah[4][4], al[4][4];
        #pragma unroll
        for (int mt = 0; mt < 4; mt++) {
            int r0 = warpM * 64 + mt * 16 + g;
            ah[mt][0] = *(const uint32_t*)&sAh[r0 * WB_STRIDE + kk];
            ah[mt][1] = *(const uint32_t*)&sAh[(r0 + 8) * WB_STRIDE + kk];
            ah[mt][2] = *(const uint32_t*)&sAh[r0 * WB_STRIDE + kk + 8];
            ah[mt][3] = *(const uint32_t*)&sAh[(r0 + 8) * WB_STRIDE + kk + 8];
            al[mt][0] = *(const uint32_t*)&sAl[r0 * WB_STRIDE + kk];
            al[mt][1] = *(const uint32_t*)&sAl[(r0 + 8) * WB_STRIDE + kk];
            al[mt][2] = *(const uint32_t*)&sAl[r0 * WB_STRIDE + kk + 8];
            al[mt][3] = *(const uint32_t*)&sAl[(r0 + 8) * WB_STRIDE + kk + 8];
        }
        uint32_t bh[4][2], bl[4][2];
        #pragma unroll
        for (int nt = 0; nt < 4; nt++) {
            int nb = warpN * 32 + nt * 8 + g;
            bh[nt][0] = *(const uint32_t*)&sBh[nb * WB_STRIDE + kk];
            bh[nt][1] = *(const uint32_t*)&sBh[nb * WB_STRIDE + kk + 8];
            bl[nt][0] = *(const uint32_t*)&sBl[nb * WB_STRIDE + kk];
            bl[nt][1] = *(const uint32_t*)&sBl[nb * WB_STRIDE + kk + 8];
        }
        #pragma unroll
        for (int mt = 0; mt < 4; mt++)
            #pragma unroll
            for (int nt = 0; nt < 4; nt++) {
                mma_bf16(acc[mt][nt], ah[mt], bh[nt]);
                mma_bf16(acc[mt][nt], ah[mt], bl[nt]);
                mma_bf16(acc[mt][nt], al[mt], bh[nt]);
            }
    }

    #pragma unroll
    for (int mt = 0; mt < 4; mt++) {
        int r0 = m0 + warpM * 64 + mt * 16 + g;
        #pragma unroll
        for (int nt = 0; nt < 4; nt++) {
            int col = n0 + warpN * 32 + nt * 8 + tg * 2;
            if (r0 < M)
                *(float2*)&C[(size_t)r0 * 16384 + col] = make_float2(acc[mt][nt][0], acc[mt][nt][1]);
            if (r0 + 8 < M)
                *(float2*)&C[(size_t)(r0 + 8) * 16384 + col] = make_float2(acc[mt][nt][2], acc[mt][nt][3]);
        }
    }
}

// ================= root GEMM: C[M,128] = A[M,128] @ Broot + bias (optional relu on A) ======
#define RT_STRIDE 136
__global__ void __launch_bounds__(128, 4)
k_root(const float* __restrict__ A, const float* __restrict__ Broot,
       const float* __restrict__ bias, float* __restrict__ C, int M, int relu_in) {
    int n_base = blockIdx.x * 64;
    int m0 = blockIdx.y * 64;
    int t = threadIdx.x, wid = t >> 5, lane = t & 31;
    int g = lane >> 2, tg = lane & 3;

    uint32_t bhf[2][8][2], blf[2][8][2];
    #pragma unroll
    for (int nt = 0; nt < 2; nt++) {
        int n = n_base + wid * 16 + nt * 8 + g;
        #pragma unroll
        for (int s = 0; s < 8; s++) {
            int k0 = s * 16 + tg * 2;
            float w0 = Broot[(k0 + 0) * 128 + n];
            float w1 = Broot[(k0 + 1) * 128 + n];
            float w2 = Broot[(k0 + 8) * 128 + n];
            float w3 = Broot[(k0 + 9) * 128 + n];
            __nv_bfloat16 h0, h1, h2, h3; float l0, l1, l2, l3;
            split_bf16(w0, h0, l0); split_bf16(w1, h1, l1);
            split_bf16(w2, h2, l2); split_bf16(w3, h3, l3);
            bhf[nt][s][0] = pack2_bf16(__bfloat162float(h0), __bfloat162float(h1));
            bhf[nt][s][1] = pack2_bf16(__bfloat162float(h2), __bfloat162float(h3));
            blf[nt][s][0] = pack2_bf16(l0, l1);
            blf[nt][s][1] = pack2_bf16(l2, l3);
        }
    }

    __shared__ __align__(16) __nv_bfloat16 s_ah[64][RT_STRIDE];
    __shared__ __align__(16) __nv_bfloat16 s_al[64][RT_STRIDE];

    #pragma unroll
    for (int e = t; e < 64 * 128; e += 128) {
        int row = e >> 7, col = e & 127;
        float v = (m0 + row < M) ? A[(size_t)(m0 + row) * 128 + col] : 0.f;
        if (relu_in) v = fmaxf(v, 0.f);
        __nv_bfloat16 h; float lo;
        split_bf16(v, h, lo);
        s_ah[row][col] = h;
        s_al[row][col] = __float2bfloat16(lo);
    }
    __syncthreads();

    float2 biasv[2];
    #pragma unroll
    for (int nt = 0; nt < 2; nt++) {
        int col = n_base + wid * 16 + nt * 8 + tg * 2;
        biasv[nt] = make_float2(bias[col], bias[col + 1]);
    }

    #pragma unroll
    for (int mt = 0; mt < 4; mt++) {
        float acc[2][4];
        #pragma unroll
        for (int nt = 0; nt < 2; nt++)
            #pragma unroll
            for (int q = 0; q < 4; q++) acc[nt][q] = 0.f;

        int ar = mt * 16 + g;
        #pragma unroll
        for (int s = 0; s < 8; s++) {
            int k0 = s * 16 + tg * 2;
            uint32_t ah[4], al[4];
            ah[0] = *(const uint32_t*)&s_ah[ar][k0];
            ah[1] = *(const uint32_t*)&s_ah[ar + 8][k0];
            ah[2] = *(const uint32_t*)&s_ah[ar][k0 + 8];
            ah[3] = *(const uint32_t*)&s_ah[ar + 8][k0 + 8];
            al[0] = *(const uint32_t*)&s_al[ar][k0];
            al[1] = *(const uint32_t*)&s_al[ar + 8][k0];
            al[2] = *(const uint32_t*)&s_al[ar][k0 + 8];
            al[3] = *(const uint32_t*)&s_al[ar + 8][k0 + 8];
            #pragma unroll
            for (int nt = 0; nt < 2; nt++) {
                mma_bf16(acc[nt], ah, bhf[nt][s]);
                mma_bf16(acc[nt], ah, blf[nt][s]);
                mma_bf16(acc[nt], al, bhf[nt][s]);
            }
        }

        int r0 = m0 + mt * 16 + g, r1 = r0 + 8;
        #pragma unroll
        for (int nt = 0; nt < 2; nt++) {
            int col = n_base + wid * 16 + nt * 8 + tg * 2;
            if (r0 < M)
                *(float2*)&C[(size_t)r0 * 128 + col] =
                    make_float2(acc[nt][0] + biasv[nt].x, acc[nt][1] + biasv[nt].y);
            if (r1 < M)
                *(float2*)&C[(size_t)r1 * 128 + col] =
                    make_float2(acc[nt][2] + biasv[nt].x, acc[nt][3] + biasv[nt].y);
        }
    }
}

// ---------------- gather + denom init ----------------
__global__ void k_gather_init(const int* __restrict__ entity, const float* __restrict__ emb) {
    int g = blockIdx.x * blockDim.x + threadIdx.x;
    if (g < NN) { g_denom0[g] = 0.f; g_denom1[g] = 0.f; }
    if (g >= NN * DD / 4) return;
    int elem = g * 4;
    int n = elem >> 7, d = elem & 127;
    int idx = entity[n];
    *(float4*)&g_X[elem] = *(const float4*)&emb[idx * DD + d];
}

// ---------------- grouping: smem counting sort ----------------
__global__ void k_hist(const int* __restrict__ etype) {
    __shared__ int h[RR];
    int t = threadIdx.x, b = blockIdx.x;
    for (int i = t; i < RR; i += GT) h[i] = 0;
    __syncthreads();
    int base = b * EPB;
    for (int i = t; i < EPB; i += GT) atomicAdd(&h[etype[base + i]], 1);
    __syncthreads();
    for (int i = t; i < RR; i += GT) g_bh[b * RR + i] = h[i];
}

__global__ void k_scan2() {
    __shared__ int tot[512];
    int t = threadIdx.x;
    int sum = 0;
    if (t < RR) {
        #pragma unroll 8
        for (int b = 0; b < GB; b++) sum += g_bh[b * RR + t];
    }
    tot[t] = (t < RR) ? sum : 0;
    __syncthreads();
    #pragma unroll
    for (int off = 1; off < 512; off <<= 1) {
        int v = (t >= off) ? tot[t - off] : 0;
        __syncthreads();
        tot[t] += v;
        __syncthreads();
    }
    if (t < RR) {
        g_offs[t + 1] = tot[t];
        int run = tot[t] - sum;     // exclusive prefix = g_offs[t]
        for (int b = 0; b < GB; b++) {
            g_bstart[b * RR + t] = run;
            run += g_bh[b * RR + t];
        }
    }
    if (t == 0) g_offs[0] = 0;
}

__global__ void k_place(const int* __restrict__ etype) {
    __shared__ int cur[RR];
    int t = threadIdx.x, b = blockIdx.x;
    for (int i = t; i < RR; i += GT) cur[i] = g_bstart[b * RR + i];
    __syncthreads();
    int base = b * EPB;
    for (int i = t; i < EPB; i += GT) {
        int e = base + i;
        int p = atomicAdd(&cur[etype[e]], 1);
        g_order[p] = e;
    }
}

// ---------------- fused logits+exp+denom (no max pass: |logit| small) ----------------
__global__ void k_alpha_exp(const float* __restrict__ X, const int* __restrict__ src,
                            const int* __restrict__ dst, const int* __restrict__ etype,
                            const float* __restrict__ wt, float* __restrict__ denom,
                            int relu_in) {
    int e = blockIdx.x * (blockDim.x >> 5) + (threadIdx.x >> 5);
    if (e >= EE) return;
    int lane = threadIdx.x & 31;
    int s = src[e], d = dst[e], r = etype[e];
    float4 xi = *(const float4*)&X[d * DD + lane * 4];
    float4 xj = *(const float4*)&X[s * DD + lane * 4];
    if (relu_in) {
        xi.x = fmaxf(xi.x, 0.f); xi.y = fmaxf(xi.y, 0.f);
        xi.z = fmaxf(xi.z, 0.f); xi.w = fmaxf(xi.w, 0.f);
        xj.x = fmaxf(xj.x, 0.f); xj.y = fmaxf(xj.y, 0.f);
        xj.z = fmaxf(xj.z, 0.f); xj.w = fmaxf(xj.w, 0.f);
    }
    float4 w  = *(const float4*)&wt[r * DD + lane * 4];
    float v = xi.x * w.x * xj.x + xi.y * w.y * xj.y + xi.z * w.z * xj.z + xi.w * w.w * xj.w;
    #pragma unroll
    for (int off = 16; off; off >>= 1) v += __shfl_xor_sync(0xffffffffu, v, off);
    if (lane == 0) {
        float a = expf(v);
        g_alpha[e] = a;
        atomicAdd(&denom[d], a);
    }
}

// ---------------- per-type messages on tensor cores ----------------
#define MSG_STRIDE 136
__global__ void __launch_bounds__(256, 2)
k_msg(const float* __restrict__ Xin, float* __restrict__ Y,
      const int* __restrict__ srcArr, const int* __restrict__ dstArr,
      const float* __restrict__ denom, int relu_in, const float* __restrict__ Wbuf) {
    int r = blockIdx.x;
    int base = g_offs[r];
    int cnt = g_offs[r + 1] - base;
    if (cnt == 0) return;
    int t = threadIdx.x, wid = t >> 5, lane = t & 31;
    int g = lane >> 2, tg = lane & 3;

    const float* Wr = Wbuf + (size_t)r * 16384;
    uint32_t bhf[2][8][2], blf[2][8][2];
    #pragma unroll
    for (int nt = 0; nt < 2; nt++) {
        int n = wid * 16 + nt * 8 + g;
        #pragma unroll
        for (int s = 0; s < 8; s++) {
            int k0 = s * 16 + tg * 2;
            float w0 = Wr[(k0 + 0) * 128 + n];
            float w1 = Wr[(k0 + 1) * 128 + n];
            float w2 = Wr[(k0 + 8) * 128 + n];
            float w3 = Wr[(k0 + 9) * 128 + n];
            __nv_bfloat16 h0, h1, h2, h3; float l0, l1, l2, l3;
            split_bf16(w0, h0, l0); split_bf16(w1, h1, l1);
            split_bf16(w2, h2, l2); split_bf16(w3, h3, l3);
            bhf[nt][s][0] = pack2_bf16(__bfloat162float(h0), __bfloat162float(h1));
            bhf[nt][s][1] = pack2_bf16(__bfloat162float(h2), __bfloat162float(h3));
            blf[nt][s][0] = pack2_bf16(l0, l1);
            blf[nt][s][1] = pack2_bf16(l2, l3);
        }
    }

    __shared__ __align__(16) __nv_bfloat16 s_xh[16][MSG_STRIDE];
    __shared__ __align__(16) __nv_bfloat16 s_xl[16][MSG_STRIDE];
    __shared__ int   dsts[16];
    __shared__ int   srcs[16];
    __shared__ float scl[16];

    for (int g0 = 0; g0 < cnt; g0 += 16) {
        __syncthreads();
        if (t < 16) {
            int j = g0 + t;
            if (j < cnt) {
                int e = g_order[base + j];
                int d = dstArr[e];
                dsts[t] = d;
                srcs[t] = srcArr[e];
                scl[t]  = g_alpha[e] / denom[d];
            } else { dsts[t] = -1; srcs[t] = 0; scl[t] = 0.f; }
        }
        __syncthreads();
        #pragma unroll
        for (int j2 = 0; j2 < 16; j2 += 2) {
            int j = j2 + (t >> 7);
            int i = t & 127;
            float v = Xin[(size_t)srcs[j] * DD + i];
            if (relu_in) v = fmaxf(v, 0.f);
            v *= scl[j];
            __nv_bfloat16 h; float lo;
            split_bf16(v, h, lo);
            s_xh[j][i] = h;
            s_xl[j][i] = __float2bfloat16(lo);
        }
        __syncthreads();

        float acc[2][4];
        #pragma unroll
        for (int nt = 0; nt < 2; nt++)
            #pragma unroll
            for (int q = 0; q < 4; q++) acc[nt][q] = 0.f;

        #pragma unroll
        for (int s = 0; s < 8; s++) {
            int k0 = s * 16 + tg * 2;
            uint32_t ah[4], al[4];
            ah[0] = *(const uint32_t*)&s_xh[g][k0];
            ah[1] = *(const uint32_t*)&s_xh[g + 8][k0];
            ah[2] = *(const uint32_t*)&s_xh[g][k0 + 8];
            ah[3] = *(const uint32_t*)&s_xh[g + 8][k0 + 8];
            al[0] = *(const uint32_t*)&s_xl[g][k0];
            al[1] = *(const uint32_t*)&s_xl[g + 8][k0];
            al[2] = *(const uint32_t*)&s_xl[g][k0 + 8];
            al[3] = *(const uint32_t*)&s_xl[g + 8][k0 + 8];
            #pragma unroll
            for (int nt = 0; nt < 2; nt++) {
                mma_bf16(acc[nt], ah, bhf[nt][s]);
                mma_bf16(acc[nt], ah, blf[nt][s]);
                mma_bf16(acc[nt], al, bhf[nt][s]);
            }
        }

        int d0 = dsts[g], d1 = dsts[g + 8];
        #pragma unroll
        for (int nt = 0; nt < 2; nt++) {
            int col = wid * 16 + nt * 8 + tg * 2;
            if (d0 >= 0) {
                atomicAdd(&Y[(size_t)d0 * DD + col],     acc[nt][0]);
                atomicAdd(&Y[(size_t)d0 * DD + col + 1], acc[nt][1]);
            }
            if (d1 >= 0) {
                atomicAdd(&Y[(size_t)d1 * DD + col],     acc[nt][2]);
                atomicAdd(&Y[(size_t)d1 * DD + col + 1], acc[nt][3]);
            }
        }
    }
}

// ---------------- launcher (forked-stream graph) ----------------
extern "C" void kernel_launch(void* const* d_in, const int* in_sizes, int n_in,
                              void* d_out, int out_size) {
    const int*   entity = (const int*)d_in[0];
    const int*   eidx   = (const int*)d_in[1];
    const int*   etype  = (const int*)d_in[2];
    const float* emb    = (const float*)d_in[3];
    const float* basis1 = (const float*)d_in[4];
    const float* att1   = (const float*)d_in[5];
    const float* w1     = (const float*)d_in[6];
    const float* root1  = (const float*)d_in[7];
    const float* bias1  = (const float*)d_in[8];
    const float* basis2 = (const float*)d_in[9];
    const float* att2   = (const float*)d_in[10];
    const float* w2     = (const float*)d_in[11];
    const float* root2  = (const float*)d_in[12];
    const float* bias2  = (const float*)d_in[13];
    float* out = (float*)d_out;
    const int* src = eidx;
    const int* dst = eidx + EE;

    float *pX = nullptr, *pH = nullptr, *pW1 = nullptr, *pW2 = nullptr, *pD0 = nullptr, *pD1 = nullptr;
    cudaGetSymbolAddress((void**)&pX, g_X);
    cudaGetSymbolAddress((void**)&pH, g_H);
    cudaGetSymbolAddress((void**)&pW1, g_W1);
    cudaGetSymbolAddress((void**)&pW2, g_W2);
    cudaGetSymbolAddress((void**)&pD0, g_denom0);
    cudaGetSymbolAddress((void**)&pD1, g_denom1);

    cudaFuncSetAttribute(k_wbuild, cudaFuncAttributeMaxDynamicSharedMemorySize, WB_SMEM);

    const int NVEC = NN * DD / 4;
    const dim3 rootGrid(2, (NN + 63) / 64);

    cudaStream_t sA;
    cudaStreamCreateWithFlags(&sA, cudaStreamNonBlocking);
    cudaEvent_t evFork, evA1, evA2;
    cudaEventCreateWithFlags(&evFork, cudaEventDisableTiming);
    cudaEventCreateWithFlags(&evA1, cudaEventDisableTiming);
    cudaEventCreateWithFlags(&evA2, cudaEventDisableTiming);

    // fork branch A off the main (legacy) stream
    cudaEventRecord(evFork, 0);
    cudaStreamWaitEvent(sA, evFork, 0);

    // branch A: grouping + both W builds (independent of X)
    k_hist<<<GB, GT, 0, sA>>>(etype);
    k_scan2<<<1, 512, 0, sA>>>();
    k_place<<<GB, GT, 0, sA>>>(etype);
    k_wbuild<<<dim3(128, 4), 256, WB_SMEM, sA>>>(att1, basis1, pW1, RR);
    cudaEventRecord(evA1, sA);
    k_wbuild<<<dim3(128, 4), 256, WB_SMEM, sA>>>(att2, basis2, pW2, RR);
    cudaEventRecord(evA2, sA);

    // main stream: feature path
    k_gather_init<<<(NVEC + 255) / 256, 256>>>(entity, emb);
    k_alpha_exp<<<EE / 4, 128>>>(pX, src, dst, etype, w1, pD0, 0);
    k_root<<<rootGrid, 128>>>(pX, root1, bias1, pH, NN, 0);
    cudaStreamWaitEvent(0, evA1, 0);                  // join: grouping + W1 ready
    k_msg<<<RR, 256>>>(pX, pH, src, dst, pD0, 0, pW1);

    k_alpha_exp<<<EE / 4, 128>>>(pH, src, dst, etype, w2, pD1, 1);
    k_root<<<rootGrid, 128>>>(pH, root2, bias2, out, NN, 1);
    cudaStreamWaitEvent(0, evA2, 0);                  // join: W2 ready (full branch A joined)
    k_msg<<<RR, 256>>>(pH, out, src, dst, pD1, 1, pW2);
}